// round 3
// baseline (speedup 1.0000x reference)
#include <cuda_runtime.h>

#define SEQ    4096
#define BATCH  16
#define HIDDEN 512
#define SCH    64          // s-chunks
#define SPC    (SEQ/SCH)   // 64 s per chunk
#define NPART  (SCH * 2)   // 2 parity lanes per chunk

// Scratch (no allocations allowed) — all fully re-written every launch.
__device__ float g_dec[BATCH * HIDDEN];            // decoder features [b][h]
__device__ float g_w[BATCH * SEQ];                 // unnormalized masked weights
__device__ float g_Z[BATCH];                       // per-batch normalizer
__device__ float g_part[NPART * BATCH * HIDDEN];   // ctx partials (deterministic)

__device__ __forceinline__ float tanh_fast(float x) {
    float y;
    asm("tanh.approx.f32 %0, %1;" : "=f"(y) : "f"(x));
    return y;
}

// ---------------------------------------------------------------------------
// K0: decoder_features[b,k] = dot(x[b,:], W[k,:]) + bias[k].
// Grid 128 = 16 b * 8 row-chunks of 64. Block 256 (8 warps), warp handles 8 rows.
// ---------------------------------------------------------------------------
__global__ void k0_dec(const float* __restrict__ x, const float* __restrict__ W,
                       const float* __restrict__ bias) {
    int b     = blockIdx.x >> 3;
    int chunk = blockIdx.x & 7;
    int tid   = threadIdx.x;               // 256
    __shared__ float xs[HIDDEN];
    xs[tid]       = x[b * HIDDEN + tid];
    xs[tid + 256] = x[b * HIDDEN + tid + 256];
    __syncthreads();

    int warp = tid >> 5, lane = tid & 31;
#pragma unroll
    for (int r = 0; r < 8; ++r) {
        int k = chunk * 64 + warp * 8 + r;
        const float4* Wr = reinterpret_cast<const float4*>(W + (size_t)k * HIDDEN);
        float acc = 0.0f;
#pragma unroll
        for (int j = 0; j < 4; ++j) {
            int idx = lane + j * 32;
            float4 wv = Wr[idx];
            int h = idx * 4;
            acc += wv.x * xs[h] + wv.y * xs[h + 1] + wv.z * xs[h + 2] + wv.w * xs[h + 3];
        }
#pragma unroll
        for (int off = 16; off; off >>= 1) acc += __shfl_down_sync(0xffffffffu, acc, off);
        if (lane == 0) g_dec[b * HIDDEN + k] = acc + bias[k];
    }
}

// ---------------------------------------------------------------------------
// KMAIN (fused k1+k3): per (b, s-chunk of 64):
//   Phase A: w[b,s] = mask * exp(score) / tss ; out_newsum = exp(score)+tss
//   Phase B: part[chunk*2+parity, b, h] = sum_{s in chunk, s%2==parity} w * enc
// Grid: 1024 = 16 b * 64 chunks. Block: 256 threads (8 warps).
// ---------------------------------------------------------------------------
__global__ void __launch_bounds__(256)
kmain(const float* __restrict__ encf, const float* __restrict__ enc,
      const float* __restrict__ mask, const float* __restrict__ tss,
      const float* __restrict__ v,    float* __restrict__ out_newsum) {
    int b     = blockIdx.x >> 6;          // 64 chunks per b
    int chunk = blockIdx.x & (SCH - 1);
    int tid   = threadIdx.x;              // 256
    int sbase = chunk * SPC;

    __shared__ float ds[HIDDEN];
    __shared__ float vs[HIDDEN];
    __shared__ float ws[SPC];
    ds[tid]       = g_dec[b * HIDDEN + tid];
    ds[tid + 256] = g_dec[b * HIDDEN + tid + 256];
    vs[tid]       = v[tid];
    vs[tid + 256] = v[tid + 256];
    __syncthreads();

    int warp = tid >> 5, lane = tid & 31;

    // ---- Phase A: 8 warps x 8 rows, in 2 batches of 4 rows ----
#pragma unroll
    for (int half = 0; half < 2; ++half) {
        int r0 = warp * 8 + half * 4;          // local row 0..63
        int s0 = sbase + r0;

        float4 ev[4][4];
#pragma unroll
        for (int i = 0; i < 4; ++i) {
            const float4* row =
                reinterpret_cast<const float4*>(encf + ((size_t)(s0 + i) * BATCH + b) * HIDDEN);
#pragma unroll
            for (int j = 0; j < 4; ++j) ev[i][j] = row[lane + j * 32];
        }

        float acc[4] = {0.f, 0.f, 0.f, 0.f};
#pragma unroll
        for (int i = 0; i < 4; ++i) {
#pragma unroll
            for (int j = 0; j < 4; ++j) {
                int h = (lane + j * 32) * 4;
                acc[i] += tanh_fast(ds[h]     + ev[i][j].x) * vs[h];
                acc[i] += tanh_fast(ds[h + 1] + ev[i][j].y) * vs[h + 1];
                acc[i] += tanh_fast(ds[h + 2] + ev[i][j].z) * vs[h + 2];
                acc[i] += tanh_fast(ds[h + 3] + ev[i][j].w) * vs[h + 3];
            }
        }
#pragma unroll
        for (int i = 0; i < 4; ++i) {
#pragma unroll
            for (int off = 16; off; off >>= 1)
                acc[i] += __shfl_down_sync(0xffffffffu, acc[i], off);
            if (lane == 0) {
                int s = s0 + i;
                float e = expf(acc[i]);
                float t = tss[b * SEQ + s];
                float w = mask[b * SEQ + s] * e / t;
                out_newsum[b * SEQ + s] = e + t;
                g_w[b * SEQ + s] = w;
                ws[r0 + i] = w;
            }
        }
    }
    __syncthreads();

    // ---- Phase B: ctx partials. 2 s-parities x 128 h4 columns. ----
    int par = tid >> 7;                  // 0/1
    int h4  = tid & 127;
    const float4* p = reinterpret_cast<const float4*>(enc)
                    + ((size_t)(sbase + par) * BATCH + b) * (HIDDEN / 4) + h4;
    const size_t stride2 = (size_t)2 * BATCH * (HIDDEN / 4);   // 2 s-steps

    float4 acc = make_float4(0.f, 0.f, 0.f, 0.f);
#pragma unroll 16
    for (int i = 0; i < SPC / 2; ++i) {
        float  w = ws[2 * i + par];
        float4 e = __ldg(p + (size_t)i * stride2);
        acc.x += w * e.x; acc.y += w * e.y; acc.z += w * e.z; acc.w += w * e.w;
    }
    reinterpret_cast<float4*>(g_part)
        [((size_t)(chunk * 2 + par) * BATCH + b) * (HIDDEN / 4) + h4] = acc;
}

// ---------------------------------------------------------------------------
// K2: Z[b] = sum_s w[b,s]. 16 blocks x 256 threads. Deterministic.
// ---------------------------------------------------------------------------
__global__ void k2_Z() {
    int b = blockIdx.x, tid = threadIdx.x;
    float acc = 0.0f;
    for (int s = tid; s < SEQ; s += 256) acc += g_w[b * SEQ + s];
    __shared__ float sm[256];
    sm[tid] = acc;
    __syncthreads();
    for (int off = 128; off; off >>= 1) {
        if (tid < off) sm[tid] += sm[tid + off];
        __syncthreads();
    }
    if (tid == 0) g_Z[b] = sm[0];
}

// ---------------------------------------------------------------------------
// K4: finalize. ctx = (sum of partials)/Z -> out[0:8192)
//               attention = w/Z           -> out[8192:73728)
// ---------------------------------------------------------------------------
__global__ void k4_final(float* __restrict__ out) {
    int i = blockIdx.x * 256 + threadIdx.x;     // 0..65535
    if (i < BATCH * HIDDEN) {
        int b = i >> 9;
        float acc = 0.0f;
#pragma unroll 8
        for (int pc = 0; pc < NPART; ++pc)
            acc += g_part[(size_t)pc * BATCH * HIDDEN + i];
        out[i] = acc / g_Z[b];
    }
    if (i < BATCH * SEQ) {
        int b = i >> 12;
        out[BATCH * HIDDEN + i] = g_w[i] / g_Z[b];
    }
}

// ---------------------------------------------------------------------------
extern "C" void kernel_launch(void* const* d_in, const int* in_sizes, int n_in,
                              void* d_out, int out_size) {
    const float* x    = (const float*)d_in[0];  // outputs_hidden [1,16,512]
    const float* enc  = (const float*)d_in[1];  // encoder_out [4096,16,512]
    const float* encf = (const float*)d_in[2];  // encoder_features [4096,16,512]
    const float* mask = (const float*)d_in[3];  // encoder_mask [16,1,4096]
    const float* tss  = (const float*)d_in[4];  // temporal_scores_sum [16,1,4096]
    const float* W    = (const float*)d_in[5];  // W_feat [512,512]
    const float* bias = (const float*)d_in[6];  // b_feat [512]
    const float* v    = (const float*)d_in[7];  // v_attn [512]

    float* out        = (float*)d_out;
    float* out_newsum = out + BATCH * HIDDEN + BATCH * SEQ;  // third output

    k0_dec <<<128,  256>>>(x, W, bias);
    kmain  <<<1024, 256>>>(encf, enc, mask, tss, v, out_newsum);
    k2_Z   <<<16,   256>>>();
    k4_final<<<256, 256>>>(out);
}

// round 4
// speedup vs baseline: 1.1100x; 1.1100x over previous
#include <cuda_runtime.h>

#define SEQ    4096
#define BATCH  16
#define HIDDEN 512
#define SCH    64          // s-chunks
#define SPC    (SEQ/SCH)   // 64 s per chunk
#define NPART  (SCH * 2)   // 128 partials (2 parity lanes per chunk)
#define NPCG   8           // pre-reduction groups
#define CTXN   (BATCH * HIDDEN)   // 8192

// Scratch (no allocations allowed) — all fully re-written every launch.
__device__ float g_dec[BATCH * HIDDEN];            // decoder features [b][h]
__device__ float g_w[BATCH * SEQ];                 // unnormalized masked weights
__device__ float g_Z[BATCH];                       // per-batch normalizer
__device__ float g_part[NPART * CTXN];             // ctx partials (deterministic)
__device__ float g_ctx2[NPCG * CTXN];              // pre-reduced ctx partials

__device__ __forceinline__ float tanh_fast(float x) {
    float y;
    asm("tanh.approx.f32 %0, %1;" : "=f"(y) : "f"(x));
    return y;
}

// ---------------------------------------------------------------------------
// K0: decoder_features[b,k] = dot(x[b,:], W[k,:]) + bias[k].
// Grid 128 = 16 b * 8 row-chunks of 64. Block 256 (8 warps), warp handles 8 rows.
// ---------------------------------------------------------------------------
__global__ void k0_dec(const float* __restrict__ x, const float* __restrict__ W,
                       const float* __restrict__ bias) {
    int b     = blockIdx.x >> 3;
    int chunk = blockIdx.x & 7;
    int tid   = threadIdx.x;               // 256
    __shared__ float xs[HIDDEN];
    xs[tid]       = x[b * HIDDEN + tid];
    xs[tid + 256] = x[b * HIDDEN + tid + 256];
    __syncthreads();

    int warp = tid >> 5, lane = tid & 31;
#pragma unroll
    for (int r = 0; r < 8; ++r) {
        int k = chunk * 64 + warp * 8 + r;
        const float4* Wr = reinterpret_cast<const float4*>(W + (size_t)k * HIDDEN);
        float acc = 0.0f;
#pragma unroll
        for (int j = 0; j < 4; ++j) {
            int idx = lane + j * 32;
            float4 wv = Wr[idx];
            int h = idx * 4;
            acc += wv.x * xs[h] + wv.y * xs[h + 1] + wv.z * xs[h + 2] + wv.w * xs[h + 3];
        }
#pragma unroll
        for (int off = 16; off; off >>= 1) acc += __shfl_down_sync(0xffffffffu, acc, off);
        if (lane == 0) g_dec[b * HIDDEN + k] = acc + bias[k];
    }
}

// ---------------------------------------------------------------------------
// KMAIN (fused scores+context): per (b, s-chunk of 64).
// Phase A: ds/vs register-cached (16 floats each per thread) — no per-term LDS.
// Phase B: ctx partials, 2 s-parities x 128 h4-columns, unroll 16.
// Grid: 1024 = 16 b * 64 chunks. Block: 256 threads (8 warps).
// ---------------------------------------------------------------------------
__global__ void __launch_bounds__(256)
kmain(const float* __restrict__ encf, const float* __restrict__ enc,
      const float* __restrict__ mask, const float* __restrict__ tss,
      const float* __restrict__ v,    float* __restrict__ out_newsum) {
    int b     = blockIdx.x >> 6;          // 64 chunks per b
    int chunk = blockIdx.x & (SCH - 1);
    int tid   = threadIdx.x;              // 256
    int sbase = chunk * SPC;

    __shared__ float ws[SPC];

    int warp = tid >> 5, lane = tid & 31;

    // Register cache of decoder features + v for this thread's 16 h-positions.
    const float4* dsg = reinterpret_cast<const float4*>(g_dec + b * HIDDEN);
    const float4* vsg = reinterpret_cast<const float4*>(v);
    float4 ds4[4], vs4[4];
#pragma unroll
    for (int j = 0; j < 4; ++j) {
        ds4[j] = dsg[lane + j * 32];
        vs4[j] = vsg[lane + j * 32];
    }

    // ---- Phase A: 8 warps x 8 rows, in 2 batches of 4 rows ----
#pragma unroll
    for (int half = 0; half < 2; ++half) {
        int r0 = warp * 8 + half * 4;          // local row 0..63
        int s0 = sbase + r0;

        float4 ev[4][4];
#pragma unroll
        for (int i = 0; i < 4; ++i) {
            const float4* row =
                reinterpret_cast<const float4*>(encf + ((size_t)(s0 + i) * BATCH + b) * HIDDEN);
#pragma unroll
            for (int j = 0; j < 4; ++j) ev[i][j] = row[lane + j * 32];
        }

        float acc[4] = {0.f, 0.f, 0.f, 0.f};
#pragma unroll
        for (int i = 0; i < 4; ++i) {
#pragma unroll
            for (int j = 0; j < 4; ++j) {
                acc[i] += tanh_fast(ds4[j].x + ev[i][j].x) * vs4[j].x;
                acc[i] += tanh_fast(ds4[j].y + ev[i][j].y) * vs4[j].y;
                acc[i] += tanh_fast(ds4[j].z + ev[i][j].z) * vs4[j].z;
                acc[i] += tanh_fast(ds4[j].w + ev[i][j].w) * vs4[j].w;
            }
        }
#pragma unroll
        for (int i = 0; i < 4; ++i) {
#pragma unroll
            for (int off = 16; off; off >>= 1)
                acc[i] += __shfl_down_sync(0xffffffffu, acc[i], off);
            if (lane == 0) {
                int s = s0 + i;
                float e = expf(acc[i]);
                float t = tss[b * SEQ + s];
                float w = mask[b * SEQ + s] * e / t;
                out_newsum[b * SEQ + s] = e + t;
                g_w[b * SEQ + s] = w;
                ws[r0 + i] = w;
            }
        }
    }
    __syncthreads();

    // ---- Phase B: ctx partials. 2 s-parities x 128 h4 columns. ----
    int par = tid >> 7;                  // 0/1
    int h4  = tid & 127;
    const float4* p = reinterpret_cast<const float4*>(enc)
                    + ((size_t)(sbase + par) * BATCH + b) * (HIDDEN / 4) + h4;
    const size_t stride2 = (size_t)2 * BATCH * (HIDDEN / 4);   // 2 s-steps

    float4 acc = make_float4(0.f, 0.f, 0.f, 0.f);
#pragma unroll 16
    for (int i = 0; i < SPC / 2; ++i) {
        float  w = ws[2 * i + par];
        float4 e = __ldg(p + (size_t)i * stride2);
        acc.x += w * e.x; acc.y += w * e.y; acc.z += w * e.z; acc.w += w * e.w;
    }
    reinterpret_cast<float4*>(g_part)
        [((size_t)(chunk * 2 + par) * BATCH + b) * (HIDDEN / 4) + h4] = acc;
}

// ---------------------------------------------------------------------------
// KRED: blocks 0..15: Z[b] = sum_s w[b,s].
//       blocks 16..271: pre-reduce 128 ctx partials into 8 groups of 16.
// ---------------------------------------------------------------------------
__global__ void kred() {
    int bid = blockIdx.x, tid = threadIdx.x;
    if (bid < 16) {
        int b = bid;
        float acc = 0.0f;
        for (int s = tid; s < SEQ; s += 256) acc += g_w[b * SEQ + s];
        __shared__ float sm[256];
        sm[tid] = acc;
        __syncthreads();
        for (int off = 128; off; off >>= 1) {
            if (tid < off) sm[tid] += sm[tid + off];
            __syncthreads();
        }
        if (tid == 0) g_Z[b] = sm[0];
    } else {
        int t   = (bid - 16) * 256 + tid;   // 0..65535
        int pcg = t >> 13;                  // 0..7
        int o   = t & (CTXN - 1);           // 0..8191
        float acc = 0.0f;
#pragma unroll
        for (int j = 0; j < NPART / NPCG; ++j)
            acc += g_part[(size_t)(pcg * (NPART / NPCG) + j) * CTXN + o];
        g_ctx2[pcg * CTXN + o] = acc;
    }
}

// ---------------------------------------------------------------------------
// K4: finalize. ctx = (sum of 8 pre-reduced)/Z -> out[0:8192)
//               attention = w/Z                -> out[8192:73728)
// ---------------------------------------------------------------------------
__global__ void k4_final(float* __restrict__ out) {
    int i = blockIdx.x * 256 + threadIdx.x;     // 0..65535
    if (i < CTXN) {
        int b = i >> 9;
        float acc = 0.0f;
#pragma unroll
        for (int pcg = 0; pcg < NPCG; ++pcg)
            acc += g_ctx2[pcg * CTXN + i];
        out[i] = acc / g_Z[b];
    }
    if (i < BATCH * SEQ) {
        int b = i >> 12;
        out[CTXN + i] = g_w[i] / g_Z[b];
    }
}

// ---------------------------------------------------------------------------
extern "C" void kernel_launch(void* const* d_in, const int* in_sizes, int n_in,
                              void* d_out, int out_size) {
    const float* x    = (const float*)d_in[0];  // outputs_hidden [1,16,512]
    const float* enc  = (const float*)d_in[1];  // encoder_out [4096,16,512]
    const float* encf = (const float*)d_in[2];  // encoder_features [4096,16,512]
    const float* mask = (const float*)d_in[3];  // encoder_mask [16,1,4096]
    const float* tss  = (const float*)d_in[4];  // temporal_scores_sum [16,1,4096]
    const float* W    = (const float*)d_in[5];  // W_feat [512,512]
    const float* bias = (const float*)d_in[6];  // b_feat [512]
    const float* v    = (const float*)d_in[7];  // v_attn [512]

    float* out        = (float*)d_out;
    float* out_newsum = out + CTXN + BATCH * SEQ;  // third output

    k0_dec  <<<128,  256>>>(x, W, bias);
    kmain   <<<1024, 256>>>(encf, enc, mask, tss, v, out_newsum);
    kred    <<<272,  256>>>();
    k4_final<<<256,  256>>>(out);
}

// round 5
// speedup vs baseline: 1.2649x; 1.1395x over previous
#include <cuda_runtime.h>

#define SEQ    4096
#define BATCH  16
#define HIDDEN 512
#define SPC    16                    // s per chunk
#define CPB    (SEQ / SPC)           // 256 chunks per batch
#define SLOTS  37                    // persistent slots per batch
#define NPART  (SLOTS * 2)           // 74 ctx partials per (b,h)
#define CTXN   (BATCH * HIDDEN)      // 8192

// Scratch (no allocations allowed) — all fully re-written every launch.
__device__ float g_dec[BATCH * HIDDEN];              // decoder features [b][h]
__device__ float g_w[BATCH * SEQ];                   // unnormalized masked weights
__device__ float g_zpart[BATCH * SLOTS];             // per-(b,slot) Z partials
__device__ float g_part[BATCH * NPART * HIDDEN];     // ctx partials [b][slot*2+par][h]

__device__ __forceinline__ float tanh_fast(float x) {
    float y;
    asm("tanh.approx.f32 %0, %1;" : "=f"(y) : "f"(x));
    return y;
}

// ---------------------------------------------------------------------------
// K0: decoder_features[b,k] = dot(x[b,:], W[k,:]) + bias[k].
// Grid 128 = 16 b * 8 row-chunks of 64. Block 256 (8 warps), warp handles 8 rows.
// ---------------------------------------------------------------------------
__global__ void k0_dec(const float* __restrict__ x, const float* __restrict__ W,
                       const float* __restrict__ bias) {
    int b     = blockIdx.x >> 3;
    int chunk = blockIdx.x & 7;
    int tid   = threadIdx.x;               // 256
    __shared__ float xs[HIDDEN];
    xs[tid]       = x[b * HIDDEN + tid];
    xs[tid + 256] = x[b * HIDDEN + tid + 256];
    __syncthreads();

    int warp = tid >> 5, lane = tid & 31;
#pragma unroll
    for (int r = 0; r < 8; ++r) {
        int k = chunk * 64 + warp * 8 + r;
        const float4* Wr = reinterpret_cast<const float4*>(W + (size_t)k * HIDDEN);
        float acc = 0.0f;
#pragma unroll
        for (int j = 0; j < 4; ++j) {
            int idx = lane + j * 32;
            float4 wv = Wr[idx];
            int h = idx * 4;
            acc += wv.x * xs[h] + wv.y * xs[h + 1] + wv.z * xs[h + 2] + wv.w * xs[h + 3];
        }
#pragma unroll
        for (int off = 16; off; off >>= 1) acc += __shfl_down_sync(0xffffffffu, acc, off);
        if (lane == 0) g_dec[b * HIDDEN + k] = acc + bias[k];
    }
}

// ---------------------------------------------------------------------------
// KMAIN: persistent fused scores+context.
// Grid 592 = 16 b * 37 slots, block 256 (8 warps). Block processes chunks
// c = slot, slot+37, ... (<256), each chunk = 16 s rows.
//   Phase A (per chunk): warp w computes scores for rows w*2, w*2+1.
//   Phase B (per chunk): 2 s-parities x 128 h4-cols, ctx accumulated in regs
//                        across ALL the block's chunks; one partial write at end.
// Z: per-lane0 accumulation -> block reduce -> g_zpart[b][slot] (deterministic).
// ---------------------------------------------------------------------------
__global__ void __launch_bounds__(256)
kmain(const float* __restrict__ encf, const float* __restrict__ enc,
      const float* __restrict__ mask, const float* __restrict__ tss,
      const float* __restrict__ v,    float* __restrict__ out_newsum) {
    int b    = blockIdx.x / SLOTS;
    int slot = blockIdx.x % SLOTS;
    int tid  = threadIdx.x;               // 256
    int warp = tid >> 5, lane = tid & 31;

    __shared__ float ws[SPC];
    __shared__ float zs[8];

    // Register cache of decoder features + v for this thread's 16 h-positions.
    const float4* dsg = reinterpret_cast<const float4*>(g_dec + b * HIDDEN);
    const float4* vsg = reinterpret_cast<const float4*>(v);
    float4 ds4[4], vs4[4];
#pragma unroll
    for (int j = 0; j < 4; ++j) {
        ds4[j] = dsg[lane + j * 32];
        vs4[j] = vsg[lane + j * 32];
    }

    // Phase-B persistent state.
    int par = tid >> 7;                   // 0/1
    int h4  = tid & 127;
    const size_t strideS = (size_t)BATCH * (HIDDEN / 4);     // float4s per s-step
    const float4* enc4 = reinterpret_cast<const float4*>(enc);
    float4 ctx = make_float4(0.f, 0.f, 0.f, 0.f);
    float zacc = 0.0f;

    for (int c = slot; c < CPB; c += SLOTS) {
        int sbase = c * SPC;
        int s0 = sbase + warp * 2;

        // ---- Phase A: 2 rows per warp ----
        float4 ev[2][4];
#pragma unroll
        for (int i = 0; i < 2; ++i) {
            const float4* row =
                reinterpret_cast<const float4*>(encf + ((size_t)(s0 + i) * BATCH + b) * HIDDEN);
#pragma unroll
            for (int j = 0; j < 4; ++j) ev[i][j] = row[lane + j * 32];
        }
        float acc[2] = {0.f, 0.f};
#pragma unroll
        for (int i = 0; i < 2; ++i) {
#pragma unroll
            for (int j = 0; j < 4; ++j) {
                acc[i] += tanh_fast(ds4[j].x + ev[i][j].x) * vs4[j].x;
                acc[i] += tanh_fast(ds4[j].y + ev[i][j].y) * vs4[j].y;
                acc[i] += tanh_fast(ds4[j].z + ev[i][j].z) * vs4[j].z;
                acc[i] += tanh_fast(ds4[j].w + ev[i][j].w) * vs4[j].w;
            }
        }
#pragma unroll
        for (int i = 0; i < 2; ++i) {
#pragma unroll
            for (int off = 16; off; off >>= 1)
                acc[i] += __shfl_down_sync(0xffffffffu, acc[i], off);
            if (lane == 0) {
                int s = s0 + i;
                float e = expf(acc[i]);
                float t = tss[b * SEQ + s];
                float w = mask[b * SEQ + s] * e / t;
                out_newsum[b * SEQ + s] = e + t;
                g_w[b * SEQ + s] = w;
                ws[warp * 2 + i] = w;
                zacc += w;
            }
        }
        __syncthreads();

        // ---- Phase B: accumulate ctx for this chunk ----
        const float4* p = enc4 + ((size_t)(sbase + par) * BATCH + b) * (HIDDEN / 4) + h4;
#pragma unroll
        for (int i = 0; i < SPC / 2; ++i) {
            float  wv = ws[2 * i + par];
            float4 e  = __ldg(p + (size_t)(2 * i) * strideS);
            ctx.x += wv * e.x; ctx.y += wv * e.y; ctx.z += wv * e.z; ctx.w += wv * e.w;
        }
        __syncthreads();   // protect ws before next chunk's phase A
    }

    // Write one ctx partial per thread.
    reinterpret_cast<float4*>(g_part)
        [((size_t)b * NPART + slot * 2 + par) * (HIDDEN / 4) + h4] = ctx;

    // Deterministic Z partial for this (b, slot).
    if (lane == 0) zs[warp] = zacc;
    __syncthreads();
    if (tid == 0) {
        float z = 0.0f;
#pragma unroll
        for (int i = 0; i < 8; ++i) z += zs[i];
        g_zpart[b * SLOTS + slot] = z;
    }
}

// ---------------------------------------------------------------------------
// K4 (fused epilogue): blocks 0..31: ctx = (sum of 74 partials)/Z -> out[0:8192)
//                      blocks 32..287: attention = w/Z -> out[8192:73728)
// Z recomputed per thread from 37 zparts (deterministic, L1-resident).
// ---------------------------------------------------------------------------
__global__ void k4_final(float* __restrict__ out) {
    int bid = blockIdx.x, tid = threadIdx.x;
    if (bid < 32) {
        int i = bid * 256 + tid;            // 0..8191
        int b = i >> 9;
        float Z = 0.0f;
#pragma unroll
        for (int j = 0; j < SLOTS; ++j) Z += g_zpart[b * SLOTS + j];
        float acc = 0.0f;
        int h = i & (HIDDEN - 1);
#pragma unroll 8
        for (int p = 0; p < NPART; ++p)
            acc += g_part[((size_t)b * NPART + p) * HIDDEN + h];
        out[i] = acc / Z;
    } else {
        int i = (bid - 32) * 256 + tid;     // 0..65535
        int b = i >> 12;
        float Z = 0.0f;
#pragma unroll
        for (int j = 0; j < SLOTS; ++j) Z += g_zpart[b * SLOTS + j];
        out[CTXN + i] = g_w[i] / Z;
    }
}

// ---------------------------------------------------------------------------
extern "C" void kernel_launch(void* const* d_in, const int* in_sizes, int n_in,
                              void* d_out, int out_size) {
    const float* x    = (const float*)d_in[0];  // outputs_hidden [1,16,512]
    const float* enc  = (const float*)d_in[1];  // encoder_out [4096,16,512]
    const float* encf = (const float*)d_in[2];  // encoder_features [4096,16,512]
    const float* mask = (const float*)d_in[3];  // encoder_mask [16,1,4096]
    const float* tss  = (const float*)d_in[4];  // temporal_scores_sum [16,1,4096]
    const float* W    = (const float*)d_in[5];  // W_feat [512,512]
    const float* bias = (const float*)d_in[6];  // b_feat [512]
    const float* v    = (const float*)d_in[7];  // v_attn [512]

    float* out        = (float*)d_out;
    float* out_newsum = out + CTXN + BATCH * SEQ;  // third output

    k0_dec  <<<128,          256>>>(x, W, bias);
    kmain   <<<BATCH * SLOTS, 256>>>(encf, enc, mask, tss, v, out_newsum);
    k4_final<<<288,          256>>>(out);
}